// round 2
// baseline (speedup 1.0000x reference)
#include <cuda_runtime.h>
#include <math.h>

#define S 8192
#define D 2048
#define WSTRIDE 4096           // W row stride (2*D)
#define NCTA_REC 128
#define ROWS_PER_CTA 16        // D / NCTA_REC
#define NCHUNK 64
#define CHUNK 128              // S / NCHUNK

// ---- scratch (no runtime allocation allowed) ----
__device__ float g_hc[(size_t)S * D];        // cummax result
__device__ float g_cp[(size_t)S * D];        // ctx_proj result
__device__ float g_chunkmax[NCHUNK * D];     // cummax phase-B scratch
__device__ int   g_flags[S * NCTA_REC];      // per-step per-CTA arrival flags

#define NEG_INF __int_as_float(0xff800000)

// ============================================================
// flag reset (required for CUDA-graph replays: flags must start 0 each run)
// ============================================================
__global__ void zero_flags_kernel() {
    int idx = blockIdx.x * blockDim.x + threadIdx.x;
    if (idx < S * NCTA_REC) g_flags[idx] = 0;
}

// ============================================================
// cummax phase A: per-(chunk, col) max
// grid: (D/256, NCHUNK), block 256
// ============================================================
__global__ void cummax_chunk_kernel(const float* __restrict__ ce) {
    int col = blockIdx.x * blockDim.x + threadIdx.x;
    int chunk = blockIdx.y;
    const float* p = ce + (size_t)chunk * CHUNK * D + col;
    float m = NEG_INF;
#pragma unroll 8
    for (int r = 0; r < CHUNK; r++) {
        m = fmaxf(m, p[(size_t)r * D]);
    }
    g_chunkmax[chunk * D + col] = m;
}

// ============================================================
// cummax phase B: exclusive prefix-max over chunks, per column
// grid: D/256, block 256
// ============================================================
__global__ void cummax_scan_kernel() {
    int col = blockIdx.x * blockDim.x + threadIdx.x;
    float run = NEG_INF;
    for (int ch = 0; ch < NCHUNK; ch++) {
        float v = g_chunkmax[ch * D + col];
        g_chunkmax[ch * D + col] = run;   // exclusive prefix
        run = fmaxf(run, v);
    }
}

// ============================================================
// cummax phase C: inclusive scan within chunk seeded by prefix
// ============================================================
__global__ void cummax_write_kernel(const float* __restrict__ ce) {
    int col = blockIdx.x * blockDim.x + threadIdx.x;
    int chunk = blockIdx.y;
    float m = g_chunkmax[chunk * D + col];
    const float* p = ce + (size_t)chunk * CHUNK * D + col;
    float*       q = g_hc + (size_t)chunk * CHUNK * D + col;
#pragma unroll 8
    for (int r = 0; r < CHUNK; r++) {
        m = fmaxf(m, p[(size_t)r * D]);
        q[(size_t)r * D] = m;
    }
}

// ============================================================
// GEMM: g_cp[t][i] = sum_j ce[t][j] * W[i][D + j] + b[i]
// CTA tile 128(t) x 128(i), K-tile 8, 256 threads, 8x8 microtile
// grid: (D/128, S/128)
// ============================================================
#define GT 128
#define GI 128
#define GK 8
#define GPAD 4

__global__ __launch_bounds__(256) void gemm_ctx_kernel(
    const float* __restrict__ A,     // context_enc
    const float* __restrict__ W,
    const float* __restrict__ bias)
{
    __shared__ float As[GK][GT + GPAD];
    __shared__ float Bs[GK][GI + GPAD];

    int tid = threadIdx.x;
    int tx = tid & 15;          // i-direction
    int ty = tid >> 4;          // t-direction
    int i0 = blockIdx.x * GI;
    int t0 = blockIdx.y * GT;

    int lr = tid >> 1;          // row within tile (0..127)
    int lk = (tid & 1) * 4;     // k offset (0 or 4)

    const float* Ap = A + (size_t)(t0 + lr) * D + lk;
    const float* Bp = W + (size_t)(i0 + lr) * WSTRIDE + D + lk;

    float acc[8][8];
#pragma unroll
    for (int m = 0; m < 8; m++)
#pragma unroll
        for (int n = 0; n < 8; n++) acc[m][n] = 0.0f;

    float4 ra = *(const float4*)Ap;
    float4 rb = *(const float4*)Bp;

    for (int kk = 0; kk < D; kk += GK) {
        As[lk + 0][lr] = ra.x; As[lk + 1][lr] = ra.y;
        As[lk + 2][lr] = ra.z; As[lk + 3][lr] = ra.w;
        Bs[lk + 0][lr] = rb.x; Bs[lk + 1][lr] = rb.y;
        Bs[lk + 2][lr] = rb.z; Bs[lk + 3][lr] = rb.w;
        __syncthreads();

        if (kk + GK < D) {
            ra = *(const float4*)(Ap + kk + GK);
            rb = *(const float4*)(Bp + kk + GK);
        }

#pragma unroll
        for (int k = 0; k < GK; k++) {
            float4 a0 = *(const float4*)&As[k][ty * 8];
            float4 a1 = *(const float4*)&As[k][ty * 8 + 4];
            float4 b0 = *(const float4*)&Bs[k][tx * 8];
            float4 b1 = *(const float4*)&Bs[k][tx * 8 + 4];
            float av[8] = {a0.x, a0.y, a0.z, a0.w, a1.x, a1.y, a1.z, a1.w};
            float bv[8] = {b0.x, b0.y, b0.z, b0.w, b1.x, b1.y, b1.z, b1.w};
#pragma unroll
            for (int m = 0; m < 8; m++)
#pragma unroll
                for (int n = 0; n < 8; n++)
                    acc[m][n] = fmaf(av[m], bv[n], acc[m][n]);
        }
        __syncthreads();
    }

    float bv[8];
#pragma unroll
    for (int n = 0; n < 8; n++) bv[n] = bias[i0 + tx * 8 + n];

#pragma unroll
    for (int m = 0; m < 8; m++) {
        size_t row = (size_t)(t0 + ty * 8 + m) * D + i0 + tx * 8;
        float4 o0 = make_float4(acc[m][0] + bv[0], acc[m][1] + bv[1],
                                acc[m][2] + bv[2], acc[m][3] + bv[3]);
        float4 o1 = make_float4(acc[m][4] + bv[4], acc[m][5] + bv[5],
                                acc[m][6] + bv[6], acc[m][7] + bv[7]);
        *(float4*)&g_cp[row]     = o0;
        *(float4*)&g_cp[row + 4] = o1;
    }
}

// ============================================================
// Recurrence: persistent, 128 CTAs x 1024 threads, W_state in registers.
// Thread (r = tid&15, c = tid>>4): output row i0+r, state cols [c*32, c*32+32).
// State ring = d_out rows (each row written once, read once per CTA).
// ============================================================
__global__ __launch_bounds__(1024, 1) void recurrence_kernel(
    const float* __restrict__ W,
    float* out)
{
    __shared__ float s_state[D];
    __shared__ float s_part[64 * 16];
    __shared__ float s_part2[8 * 16];

    int tid = threadIdx.x;
    int cta = blockIdx.x;
    int r = tid & 15;
    int c = tid >> 4;
    int i0 = cta * ROWS_PER_CTA;

    // preload W_state slice into registers: W[i0+r][c*32 .. c*32+32)
    float w[32];
    const float* wp = W + (size_t)(i0 + r) * WSTRIDE + c * 32;
#pragma unroll
    for (int k = 0; k < 32; k += 4) {
        float4 v = *(const float4*)(wp + k);
        w[k] = v.x; w[k + 1] = v.y; w[k + 2] = v.z; w[k + 3] = v.w;
    }

    for (int t = 0; t < S; t++) {
        // ---- obtain previous state into smem ----
        if (t == 0) {
            if (tid < 512) {
                float4 mone = make_float4(-1.f, -1.f, -1.f, -1.f);
                *(float4*)&s_state[tid * 4] = mone;
            }
        } else {
            if (tid < NCTA_REC) {
                volatile int* f = &g_flags[(t - 1) * NCTA_REC + tid];
                while (*f == 0) { }
                __threadfence();          // acquire for the polled flag
            }
            __syncthreads();
            if (tid < 512) {
                *(float4*)&s_state[tid * 4] =
                    *(const float4*)&out[(size_t)(t - 1) * D + tid * 4];
            }
        }

        // finalize-thread prefetches (latency hidden behind compute)
        float hcv = 0.0f, cpv = 0.0f;
        if (tid < ROWS_PER_CTA) {
            hcv = g_hc[(size_t)t * D + i0 + tid];
            cpv = g_cp[(size_t)t * D + i0 + tid];
        }
        __syncthreads();

        // ---- partial dot product: 32 MACs, W in regs, state from smem ----
        float acc0 = 0.0f, acc1 = 0.0f;
        const float* sp = s_state + c * 32;
#pragma unroll
        for (int k = 0; k < 32; k += 8) {
            float4 v0 = *(const float4*)(sp + k);
            float4 v1 = *(const float4*)(sp + k + 4);
            acc0 = fmaf(w[k + 0], v0.x, acc0);
            acc0 = fmaf(w[k + 1], v0.y, acc0);
            acc0 = fmaf(w[k + 2], v0.z, acc0);
            acc0 = fmaf(w[k + 3], v0.w, acc0);
            acc1 = fmaf(w[k + 4], v1.x, acc1);
            acc1 = fmaf(w[k + 5], v1.y, acc1);
            acc1 = fmaf(w[k + 6], v1.z, acc1);
            acc1 = fmaf(w[k + 7], v1.w, acc1);
        }
        s_part[c * 16 + r] = acc0 + acc1;
        __syncthreads();

        // ---- reduction layer 1: 64 -> 8 partials per row ----
        if (tid < 128) {
            int rr = tid & 15, kq = tid >> 4;
            float s = 0.0f;
#pragma unroll
            for (int m = 0; m < 8; m++) s += s_part[(kq * 8 + m) * 16 + rr];
            s_part2[kq * 16 + rr] = s;
        }
        __syncthreads();

        // ---- finalize: reduce 8, sigmoid, gate, store ----
        if (tid < ROWS_PER_CTA) {
            float s = 0.0f;
#pragma unroll
            for (int m = 0; m < 8; m++) s += s_part2[m * 16 + tid];
            float x = s + cpv;
            float g = 1.0f / (1.0f + __expf(-x));
            float ns = hcv * g;
            out[(size_t)t * D + i0 + tid] = ns;
            if (t == S - 1) out[(size_t)S * D + i0 + tid] = ns;  // final_state
        }
        __syncthreads();   // all 16 row-stores done before the flag release

        if (tid == 0) {
            __threadfence();
            *((volatile int*)&g_flags[t * NCTA_REC + cta]) = 1;
        }
    }
}

// ============================================================
extern "C" void kernel_launch(void* const* d_in, const int* in_sizes, int n_in,
                              void* d_out, int out_size) {
    const float* ce = (const float*)d_in[0];   // (S, D)
    const float* W  = (const float*)d_in[1];   // (D, 2D)
    const float* b  = (const float*)d_in[2];   // (D,)
    float* out = (float*)d_out;                // (S*D + D) floats

    zero_flags_kernel<<<(S * NCTA_REC + 1023) / 1024, 1024>>>();

    dim3 cgrid(D / 256, NCHUNK);
    cummax_chunk_kernel<<<cgrid, 256>>>(ce);
    cummax_scan_kernel<<<D / 256, 256>>>();
    cummax_write_kernel<<<cgrid, 256>>>(ce);

    dim3 ggrid(D / GI, S / GT);
    gemm_ctx_kernel<<<ggrid, 256>>>(ce, W, b);

    recurrence_kernel<<<NCTA_REC, 1024>>>(W, out);
}